// round 15
// baseline (speedup 1.0000x reference)
#include <cuda_runtime.h>
#include <math.h>
#include <stdint.h>

#define B_  4
#define S_  2048
#define H_  768
#define NH_ 12
#define D_  64
#define SCALE_ 0.125f          // 1/sqrt(64)
#define LOG2E_ 1.44269504089f

// Scratch. Q/K layout [b][h][s][d]; VT layout [b][h][d][s]
__device__ float g_Q[(size_t)B_ * NH_ * S_ * D_];
__device__ float g_K[(size_t)B_ * NH_ * S_ * D_];
__device__ float g_VT[(size_t)B_ * NH_ * D_ * S_];
// Transposed weights [qkv][h][d][H] (tf32-rounded)
__device__ float g_WT[(size_t)3 * NH_ * D_ * H_];

// ---------------------------------------------------------------------------
__device__ __forceinline__ uint32_t f2tf32(float f) {
    uint32_t u;
    asm("cvt.rna.tf32.f32 %0, %1;" : "=r"(u) : "f"(f));
    return u;
}
__device__ __forceinline__ float ex2(float x) {
    float r;
    asm("ex2.approx.f32 %0, %1;" : "=f"(r) : "f"(x));
    return r;
}
__device__ __forceinline__ void mma_tf32(float c[4], uint32_t a0, uint32_t a1,
                                         uint32_t a2, uint32_t a3,
                                         uint32_t b0, uint32_t b1) {
    asm volatile(
        "mma.sync.aligned.m16n8k8.row.col.f32.tf32.tf32.f32 "
        "{%0,%1,%2,%3}, {%4,%5,%6,%7}, {%8,%9}, {%0,%1,%2,%3};"
        : "+f"(c[0]), "+f"(c[1]), "+f"(c[2]), "+f"(c[3])
        : "r"(a0), "r"(a1), "r"(a2), "r"(a3), "r"(b0), "r"(b1));
}
// One ldmatrix.x4: 4 m8n8(b16) tiles = 4 fragment registers.
__device__ __forceinline__ void ldsm_x4(uint32_t r[4], uint32_t addr) {
    asm volatile(
        "ldmatrix.sync.aligned.m8n8.x4.shared.b16 {%0,%1,%2,%3}, [%4];"
        : "=r"(r[0]), "=r"(r[1]), "=r"(r[2]), "=r"(r[3]) : "r"(addr));
}
__device__ __forceinline__ void cp16(uint32_t smem, const void* g) {
    asm volatile("cp.async.cg.shared.global [%0], [%1], 16;"
                 :: "r"(smem), "l"(g));
}
#define CP_COMMIT() asm volatile("cp.async.commit_group;")
#define CP_WAIT(n)  asm volatile("cp.async.wait_group %0;" :: "n"(n))

// ---------------------------------------------------------------------------
// Transpose W[h][H][D] -> g_WT[qkv][h][D][H], tf32-rounded. grid (48,36), 256t.
// ---------------------------------------------------------------------------
__global__ __launch_bounds__(256) void transpose_W(
    const float* __restrict__ Wq, const float* __restrict__ Wk,
    const float* __restrict__ Wv)
{
    const int qkv = blockIdx.y / NH_;
    const int h   = blockIdx.y % NH_;
    const float* W = (qkv == 0 ? Wq : (qkv == 1 ? Wk : Wv)) + (size_t)h * H_ * D_;
    float* WT = g_WT + (size_t)blockIdx.y * D_ * H_;

    const int kt = (blockIdx.x >> 1) * 32;   // k-tile (H dim)
    const int nt = (blockIdx.x & 1) * 32;    // n-tile (D dim)

    __shared__ float t[32][33];
    const int r  = threadIdx.x >> 3;          // 0..31
    const int c4 = (threadIdx.x & 7) * 4;     // 0,4,..28

    float4 v = *(const float4*)&W[(size_t)(kt + r) * D_ + nt + c4];
    t[r][c4 + 0] = v.x; t[r][c4 + 1] = v.y; t[r][c4 + 2] = v.z; t[r][c4 + 3] = v.w;
    __syncthreads();
    float4 o;
    o.x = __uint_as_float(f2tf32(t[c4 + 0][r]));
    o.y = __uint_as_float(f2tf32(t[c4 + 1][r]));
    o.z = __uint_as_float(f2tf32(t[c4 + 2][r]));
    o.w = __uint_as_float(f2tf32(t[c4 + 3][r]));
    *(float4*)&WT[(size_t)(nt + r) * H_ + kt + c4] = o;
}

// ---------------------------------------------------------------------------
// QKV projection (per group+batch launch): grid (16, 3), blockIdx.y = qkv.
// 512 thr (16 warps), block 128x256 (4 heads of group `grp`), warp 32x64.
// Processes only batch `bb`'s 2048 rows.
// ---------------------------------------------------------------------------
#define APITCH 36   // 36 % 32 == 4; row stride 144B = 9*16B -> LDSM conflict-free
#define KSTAGES (H_ / 32)   // 24
#define PROJ_SMEM ((2 * 128 * APITCH + 2 * 256 * APITCH) * 4)   // 110592 B
__global__ __launch_bounds__(512) void qkv_proj_tc(
    const float* __restrict__ e1, const float* __restrict__ e2,
    const float* __restrict__ e3,
    const float* __restrict__ bq, const float* __restrict__ bk,
    const float* __restrict__ bv, int grp, int bb)
{
    const int qkv = blockIdx.y;

    const float* WT   = g_WT + ((size_t)(qkv * NH_ + grp * 4)) * D_ * H_;
    const float* bias = (qkv == 0 ? bq : (qkv == 1 ? bk : bv)) + grp * 4 * D_;
    const float* x    = (grp == 0 ? e1 : (grp == 1 ? e2 : e3))
                        + (size_t)bb * S_ * H_;

    const int m0  = blockIdx.x * 128;      // row within batch bb
    const int tid = threadIdx.x;
    const int w    = tid >> 5;
    const int lane = tid & 31;
    const int g    = lane >> 2;
    const int c    = lane & 3;
    const int m0w  = (w & 3) * 32;
    const int n0w  = (w >> 2) * 64;

    const int mrow = lane & 7;
    const int msel = lane >> 3;
    const int a_row = (msel & 1) * 8 + mrow;
    const int a_col = (msel >> 1) * 4;
    const int b_row = (msel >> 1) * 8 + mrow;
    const int b_col = (msel & 1) * 4;

    extern __shared__ float psm[];
    float* As0 = psm;
    float* Bs0 = psm + 2 * 128 * APITCH;
    const uint32_t AsU[2] = { (uint32_t)__cvta_generic_to_shared(As0),
                              (uint32_t)__cvta_generic_to_shared(As0 + 128 * APITCH) };
    const uint32_t BsU[2] = { (uint32_t)__cvta_generic_to_shared(Bs0),
                              (uint32_t)__cvta_generic_to_shared(Bs0 + 256 * APITCH) };

    const int f_row = tid >> 3;
    const int f_c4  = (tid & 7) * 4;

    #pragma unroll
    for (int p = 0; p < 2; p++) {
        int row = f_row + p * 64;
        cp16(AsU[0] + (uint32_t)((row * APITCH + f_c4) * 4),
             &x[(size_t)(m0 + row) * H_ + f_c4]);
    }
    #pragma unroll
    for (int p = 0; p < 4; p++) {
        int row = f_row + p * 64;
        cp16(BsU[0] + (uint32_t)((row * APITCH + f_c4) * 4),
             &WT[(size_t)row * H_ + f_c4]);
    }
    CP_COMMIT();

    float Cf[2][8][4] = {};

    for (int s = 0; s < KSTAGES; s++) {
        CP_WAIT(0);
        __syncthreads();

        if (s + 1 < KSTAGES) {
            const int kc = (s + 1) * 32;
            const int nb = (s + 1) & 1;
            #pragma unroll
            for (int p = 0; p < 2; p++) {
                int row = f_row + p * 64;
                cp16(AsU[nb] + (uint32_t)((row * APITCH + f_c4) * 4),
                     &x[(size_t)(m0 + row) * H_ + kc + f_c4]);
            }
            #pragma unroll
            for (int p = 0; p < 4; p++) {
                int row = f_row + p * 64;
                cp16(BsU[nb] + (uint32_t)((row * APITCH + f_c4) * 4),
                     &WT[(size_t)row * H_ + kc + f_c4]);
            }
            CP_COMMIT();
        }

        const uint32_t aBase = AsU[s & 1];
        const uint32_t bBase = BsU[s & 1];
        #pragma unroll
        for (int k0 = 0; k0 < 32; k0 += 8) {
            uint32_t a[2][4], b[4][4];
            #pragma unroll
            for (int ma = 0; ma < 2; ma++)
                ldsm_x4(a[ma], aBase + (uint32_t)(((m0w + ma * 16 + a_row) * APITCH
                                                   + k0 + a_col) * 4));
            #pragma unroll
            for (int p = 0; p < 4; p++)
                ldsm_x4(b[p], bBase + (uint32_t)(((n0w + p * 16 + b_row) * APITCH
                                                  + k0 + b_col) * 4));
            #pragma unroll
            for (int na = 0; na < 8; na++) {
                uint32_t b0 = b[na >> 1][(na & 1) * 2];
                uint32_t b1 = b[na >> 1][(na & 1) * 2 + 1];
                #pragma unroll
                for (int ma = 0; ma < 2; ma++)
                    mma_tf32(Cf[ma][na], a[ma][0], a[ma][1], a[ma][2], a[ma][3],
                             b0, b1);
            }
        }
    }

    const int h = grp * 4 + (w >> 2);
    if (qkv < 2) {
        float* out = (qkv == 0) ? g_Q : g_K;
        const float scale = (qkv == 0) ? (SCALE_ * LOG2E_) : 1.0f;
        #pragma unroll
        for (int ma = 0; ma < 2; ma++) {
            #pragma unroll
            for (int na = 0; na < 8; na++) {
                int d0 = na * 8 + 2 * c;
                float b0 = bias[n0w + d0], b1 = bias[n0w + d0 + 1];
                #pragma unroll
                for (int half = 0; half < 2; half++) {
                    int sq = m0 + m0w + ma * 16 + g + half * 8;   // row in batch
                    size_t base = (((size_t)bb * NH_ + h) * S_ + sq) * D_ + d0;
                    float2 o;
                    o.x = __uint_as_float(f2tf32((Cf[ma][na][half * 2 + 0] + b0) * scale));
                    o.y = __uint_as_float(f2tf32((Cf[ma][na][half * 2 + 1] + b1) * scale));
                    *(float2*)&out[base] = o;
                }
            }
        }
    } else {
        #pragma unroll
        for (int ma = 0; ma < 2; ma++) {
            #pragma unroll
            for (int na = 0; na < 8; na++) {
                int d0 = na * 8 + 2 * c;
                float b0 = bias[n0w + d0], b1 = bias[n0w + d0 + 1];
                #pragma unroll
                for (int half = 0; half < 2; half++) {
                    int sq = m0 + m0w + ma * 16 + g + half * 8;
                    float* VT = g_VT + ((size_t)bb * NH_ + h) * D_ * S_;
                    VT[(size_t)d0 * S_ + sq] =
                        __uint_as_float(f2tf32(Cf[ma][na][half * 2 + 0] + b0));
                    VT[(size_t)(d0 + 1) * S_ + sq] =
                        __uint_as_float(f2tf32(Cf[ma][na][half * 2 + 1] + b1));
                }
            }
        }
    }
}

// ---------------------------------------------------------------------------
// Flash attention (per group+batch launch): grid (16, 4), blockIdx.y = e
// (head = grp*4 + e). 128 thr (4 warps), warp 32 q-rows x 64 keys.
// cp.async ping pipeline, Q-hoist + Ps alias, exp2 softmax. Smem 69632 B.
// ---------------------------------------------------------------------------
#define PITCH 68    // 68 % 32 == 4; row stride 272B = 17*16B -> LDSM conflict-free
__global__ __launch_bounds__(128) void attn_tc(float* __restrict__ out,
                                               int grp, int bb)
{
    const int h  = grp * 4 + blockIdx.y;
    const int bh = bb * NH_ + h;
    const int q0 = blockIdx.x * 128;

    extern __shared__ float sm[];
    float* Qs = sm;                  // [128][PITCH]  (q, d) -> becomes Ps
    float* Ks = Qs + 128 * PITCH;    // [64][PITCH]   (key, d)
    float* Vt = Ks + 64 * PITCH;     // [64][PITCH]   (d, key)
    float* Ps = Qs;                  // alias: Qs dead after fragment hoist
    const uint32_t QsU = (uint32_t)__cvta_generic_to_shared(Qs);
    const uint32_t KsU = (uint32_t)__cvta_generic_to_shared(Ks);
    const uint32_t VtU = (uint32_t)__cvta_generic_to_shared(Vt);
    const uint32_t PsU = QsU;

    const float* Qg  = g_Q  + (size_t)bh * S_ * D_;
    const float* Kg  = g_K  + (size_t)bh * S_ * D_;
    const float* VTg = g_VT + (size_t)bh * D_ * S_;

    const int tid  = threadIdx.x;
    const int w    = tid >> 5;
    const int lane = tid & 31;
    const int g    = lane >> 2;
    const int c    = lane & 3;
    const int m0   = w * 32;

    const int mrow = lane & 7;
    const int msel = lane >> 3;
    const int a_row = (msel & 1) * 8 + mrow;
    const int a_col = (msel >> 1) * 4;
    const int b_row = (msel >> 1) * 8 + mrow;
    const int b_col = (msel & 1) * 4;

    const uint32_t aQ0 = QsU + (uint32_t)(((m0 + a_row) * PITCH + a_col) * 4);
    const uint32_t aQ1 = QsU + (uint32_t)(((m0 + 16 + a_row) * PITCH + a_col) * 4);
    const uint32_t aP0 = PsU + (uint32_t)(((m0 + a_row) * PITCH + a_col) * 4);
    const uint32_t aP1 = PsU + (uint32_t)(((m0 + 16 + a_row) * PITCH + a_col) * 4);

    const int f_row = tid >> 4;            // +p*8 rows
    const int f_c4  = (tid & 15) * 4;

    // -------- prologue: start K0/V0 copies, then load Q --------
    #pragma unroll
    for (int p = 0; p < 8; p++) {
        int row = f_row + p * 8;
        cp16(KsU + (uint32_t)((row * PITCH + f_c4) * 4),
             &Kg[(size_t)row * D_ + f_c4]);
        cp16(VtU + (uint32_t)((row * PITCH + f_c4) * 4),
             &VTg[(size_t)row * S_ + f_c4]);
    }
    CP_COMMIT();

    #pragma unroll
    for (int p = 0; p < 16; p++) {
        int idx = tid + p * 128;
        int row = idx >> 4;
        int c4  = (idx & 15) * 4;
        float4 v = *(const float4*)&Qg[(size_t)(q0 + row) * D_ + c4];
        float* d = &Qs[row * PITCH + c4];
        d[0] = __uint_as_float(f2tf32(v.x));
        d[1] = __uint_as_float(f2tf32(v.y));
        d[2] = __uint_as_float(f2tf32(v.z));
        d[3] = __uint_as_float(f2tf32(v.w));
    }

    float m_i[2][2], l_i[2][2];
    #pragma unroll
    for (int ma = 0; ma < 2; ma++)
        #pragma unroll
        for (int hf = 0; hf < 2; hf++) { m_i[ma][hf] = -INFINITY; l_i[ma][hf] = 0.0f; }
    float O[2][8][4] = {};

    CP_WAIT(0);
    __syncthreads();   // K0, V0, Q all visible

    // Hoist Q fragments to registers (Ps reuse of Qs is ordered by the
    // tile-0 post-QK __syncthreads).
    uint32_t qf[2][8][4];
    #pragma unroll
    for (int ks = 0; ks < 8; ks++) {
        ldsm_x4(qf[0][ks], aQ0 + (uint32_t)(ks * 32));
        ldsm_x4(qf[1][ks], aQ1 + (uint32_t)(ks * 32));
    }

    for (int kt = 0; kt < S_; kt += 64) {
        const int ktn = (kt + 64 < S_) ? kt + 64 : kt;

        // ---- S = Q K^T ----
        float Sf[2][8][4] = {};
        #pragma unroll
        for (int k0 = 0; k0 < 64; k0 += 8) {
            const int ks = k0 >> 3;
            uint32_t b[4][4];
            #pragma unroll
            for (int p = 0; p < 4; p++)
                ldsm_x4(b[p], KsU + (uint32_t)(((p * 16 + b_row) * PITCH
                                                + k0 + b_col) * 4));
            #pragma unroll
            for (int na = 0; na < 8; na++) {
                uint32_t b0 = b[na >> 1][(na & 1) * 2];
                uint32_t b1 = b[na >> 1][(na & 1) * 2 + 1];
                #pragma unroll
                for (int ma = 0; ma < 2; ma++)
                    mma_tf32(Sf[ma][na], qf[ma][ks][0], qf[ma][ks][1],
                             qf[ma][ks][2], qf[ma][ks][3], b0, b1);
            }
        }
        __syncthreads();   // all warps done reading Ks (and tile-0 hoist done)

        // ---- prefetch K_{i+1} ----
        #pragma unroll
        for (int p = 0; p < 8; p++) {
            int row = f_row + p * 8;
            cp16(KsU + (uint32_t)((row * PITCH + f_c4) * 4),
                 &Kg[(size_t)(ktn + row) * D_ + f_c4]);
        }
        CP_COMMIT();

        // ---- online softmax (exp2 domain) ----
        #pragma unroll
        for (int ma = 0; ma < 2; ma++) {
            #pragma unroll
            for (int hf = 0; hf < 2; hf++) {
                float mx = -INFINITY;
                #pragma unroll
                for (int na = 0; na < 8; na++)
                    mx = fmaxf(mx, fmaxf(Sf[ma][na][hf * 2], Sf[ma][na][hf * 2 + 1]));
                mx = fmaxf(mx, __shfl_xor_sync(0xffffffffu, mx, 1));
                mx = fmaxf(mx, __shfl_xor_sync(0xffffffffu, mx, 2));
                float mnew  = fmaxf(m_i[ma][hf], mx);
                float alpha = ex2(m_i[ma][hf] - mnew);
                m_i[ma][hf] = mnew;
                float rs = 0.0f;
                #pragma unroll
                for (int na = 0; na < 8; na++) {
                    float p0 = ex2(Sf[ma][na][hf * 2]     - mnew);
                    float p1 = ex2(Sf[ma][na][hf * 2 + 1] - mnew);
                    Sf[ma][na][hf * 2]     = p0;
                    Sf[ma][na][hf * 2 + 1] = p1;
                    rs += p0 + p1;
                }
                rs += __shfl_xor_sync(0xffffffffu, rs, 1);
                rs += __shfl_xor_sync(0xffffffffu, rs, 2);
                l_i[ma][hf] = l_i[ma][hf] * alpha + rs;
                #pragma unroll
                for (int na = 0; na < 8; na++) {
                    O[ma][na][hf * 2]     *= alpha;
                    O[ma][na][hf * 2 + 1] *= alpha;
                }
            }
        }

        // ---- stage P (tf32-rounded) into Ps (= old Qs region) ----
        #pragma unroll
        for (int ma = 0; ma < 2; ma++) {
            int r = m0 + ma * 16 + g;
            #pragma unroll
            for (int na = 0; na < 8; na++) {
                float2 p0, p1;
                p0.x = __uint_as_float(f2tf32(Sf[ma][na][0]));
                p0.y = __uint_as_float(f2tf32(Sf[ma][na][1]));
                p1.x = __uint_as_float(f2tf32(Sf[ma][na][2]));
                p1.y = __uint_as_float(f2tf32(Sf[ma][na][3]));
                *(float2*)&Ps[r * PITCH + na * 8 + 2 * c]       = p0;
                *(float2*)&Ps[(r + 8) * PITCH + na * 8 + 2 * c] = p1;
            }
        }

        CP_WAIT(1);          // V_i done; K_{i+1} may stay pending
        __syncthreads();     // Vt visible; Ps ordered

        // ---- O += P V ----
        #pragma unroll
        for (int k0 = 0; k0 < 64; k0 += 8) {
            uint32_t a[2][4], b[4][4];
            ldsm_x4(a[0], aP0 + (uint32_t)(k0 * 4));
            ldsm_x4(a[1], aP1 + (uint32_t)(k0 * 4));
            #pragma unroll
            for (int p = 0; p < 4; p++)
                ldsm_x4(b[p], VtU + (uint32_t)(((p * 16 + b_row) * PITCH
                                                + k0 + b_col) * 4));
            #pragma unroll
            for (int na = 0; na < 8; na++) {
                uint32_t b0 = b[na >> 1][(na & 1) * 2];
                uint32_t b1 = b[na >> 1][(na & 1) * 2 + 1];
                #pragma unroll
                for (int ma = 0; ma < 2; ma++)
                    mma_tf32(O[ma][na], a[ma][0], a[ma][1], a[ma][2], a[ma][3],
                             b0, b1);
            }
        }
        __syncthreads();   // all warps done reading Vt

        // ---- prefetch V_{i+1} ----
        #pragma unroll
        for (int p = 0; p < 8; p++) {
            int row = f_row + p * 8;
            cp16(VtU + (uint32_t)((row * PITCH + f_c4) * 4),
                 &VTg[(size_t)row * S_ + ktn + f_c4]);
        }
        CP_COMMIT();

        CP_WAIT(1);          // K_{i+1} done; V_{i+1} may stay pending
        __syncthreads();
    }

    // Epilogue: normalize and write out[b][s][h*64+d]
    #pragma unroll
    for (int ma = 0; ma < 2; ma++) {
        float inv0 = 1.0f / l_i[ma][0];
        float inv1 = 1.0f / l_i[ma][1];
        int r0 = q0 + m0 + ma * 16 + g;
        #pragma unroll
        for (int na = 0; na < 8; na++) {
            int d0 = na * 8 + 2 * c;
            size_t base0 = ((size_t)bb * S_ + r0) * (NH_ * D_) + h * D_ + d0;
            float2 o0; o0.x = O[ma][na][0] * inv0; o0.y = O[ma][na][1] * inv0;
            *(float2*)&out[base0] = o0;
            size_t base1 = ((size_t)bb * S_ + r0 + 8) * (NH_ * D_) + h * D_ + d0;
            float2 o1; o1.x = O[ma][na][2] * inv1; o1.y = O[ma][na][3] * inv1;
            *(float2*)&out[base1] = o1;
        }
    }
}

// ---------------------------------------------------------------------------
extern "C" void kernel_launch(void* const* d_in, const int* in_sizes, int n_in,
                              void* d_out, int out_size)
{
    const float* e1 = (const float*)d_in[0];
    const float* e2 = (const float*)d_in[1];
    const float* e3 = (const float*)d_in[2];
    const float* Wq = (const float*)d_in[3];
    const float* bq = (const float*)d_in[4];
    const float* Wk = (const float*)d_in[5];
    const float* bk = (const float*)d_in[6];
    const float* Wv = (const float*)d_in[7];
    const float* bv = (const float*)d_in[8];
    float* out = (float*)d_out;

    const int attn_smem = 256 * PITCH * sizeof(float);   // 69632 B

    // Same resource footprint as the R12 passing run: 2 created streams,
    // 3 events. Stream g owns group g and interleaves its 4 batches:
    // proj(g,0), attn(g,0), proj(g,1), attn(g,1), ...
    static bool init_done = false;
    static cudaStream_t s1, s2;
    static cudaEvent_t evFork, evJ1, evJ2;
    if (!init_done) {
        cudaFuncSetAttribute(attn_tc, cudaFuncAttributeMaxDynamicSharedMemorySize,
                             attn_smem);
        cudaFuncSetAttribute(qkv_proj_tc, cudaFuncAttributeMaxDynamicSharedMemorySize,
                             PROJ_SMEM);
        cudaStreamCreateWithFlags(&s1, cudaStreamNonBlocking);
        cudaStreamCreateWithFlags(&s2, cudaStreamNonBlocking);
        cudaEventCreateWithFlags(&evFork, cudaEventDisableTiming);
        cudaEventCreateWithFlags(&evJ1, cudaEventDisableTiming);
        cudaEventCreateWithFlags(&evJ2, cudaEventDisableTiming);
        init_done = true;
    }

    transpose_W<<<dim3(48, 36), 256>>>(Wq, Wk, Wv);
    cudaEventRecord(evFork, 0);
    cudaStreamWaitEvent(s1, evFork, 0);
    cudaStreamWaitEvent(s2, evFork, 0);

    dim3 gproj(S_ / 128, 3);   // 48 CTAs per (grp, bb)
    dim3 gattn(S_ / 128, 4);   // 64 CTAs per (grp, bb)
    cudaStream_t strm[3] = { (cudaStream_t)0, s1, s2 };
    for (int bb = 0; bb < B_; bb++) {
        for (int grp = 0; grp < 3; grp++) {
            cudaStream_t s = strm[grp];
            qkv_proj_tc<<<gproj, 512, PROJ_SMEM, s>>>(e1, e2, e3, bq, bk, bv,
                                                      grp, bb);
            attn_tc<<<gattn, 128, attn_smem, s>>>(out, grp, bb);
        }
    }

    cudaEventRecord(evJ1, s1);
    cudaEventRecord(evJ2, s2);
    cudaStreamWaitEvent(0, evJ1, 0);
    cudaStreamWaitEvent(0, evJ2, 0);
}

// round 16
// speedup vs baseline: 1.3382x; 1.3382x over previous
#include <cuda_runtime.h>
#include <math.h>
#include <stdint.h>

#define B_  4
#define S_  2048
#define H_  768
#define NH_ 12
#define D_  64
#define SCALE_ 0.125f          // 1/sqrt(64)
#define LOG2E_ 1.44269504089f

// Scratch. Q/K layout [b][h][s][d]; VT layout [b][h][d][s]
__device__ float g_Q[(size_t)B_ * NH_ * S_ * D_];
__device__ float g_K[(size_t)B_ * NH_ * S_ * D_];
__device__ float g_VT[(size_t)B_ * NH_ * D_ * S_];
// Transposed weights [qkv][h][d][H] (tf32-rounded)
__device__ float g_WT[(size_t)3 * NH_ * D_ * H_];

// ---------------------------------------------------------------------------
__device__ __forceinline__ uint32_t f2tf32(float f) {
    uint32_t u;
    asm("cvt.rna.tf32.f32 %0, %1;" : "=r"(u) : "f"(f));
    return u;
}
__device__ __forceinline__ float ex2(float x) {
    float r;
    asm("ex2.approx.f32 %0, %1;" : "=f"(r) : "f"(x));
    return r;
}
__device__ __forceinline__ void mma_tf32(float c[4], uint32_t a0, uint32_t a1,
                                         uint32_t a2, uint32_t a3,
                                         uint32_t b0, uint32_t b1) {
    asm volatile(
        "mma.sync.aligned.m16n8k8.row.col.f32.tf32.tf32.f32 "
        "{%0,%1,%2,%3}, {%4,%5,%6,%7}, {%8,%9}, {%0,%1,%2,%3};"
        : "+f"(c[0]), "+f"(c[1]), "+f"(c[2]), "+f"(c[3])
        : "r"(a0), "r"(a1), "r"(a2), "r"(a3), "r"(b0), "r"(b1));
}
// One ldmatrix.x4: 4 m8n8(b16) tiles = 4 fragment registers.
__device__ __forceinline__ void ldsm_x4(uint32_t r[4], uint32_t addr) {
    asm volatile(
        "ldmatrix.sync.aligned.m8n8.x4.shared.b16 {%0,%1,%2,%3}, [%4];"
        : "=r"(r[0]), "=r"(r[1]), "=r"(r[2]), "=r"(r[3]) : "r"(addr));
}
__device__ __forceinline__ void cp16(uint32_t smem, const void* g) {
    asm volatile("cp.async.cg.shared.global [%0], [%1], 16;"
                 :: "r"(smem), "l"(g));
}
#define CP_COMMIT() asm volatile("cp.async.commit_group;")
#define CP_WAIT(n)  asm volatile("cp.async.wait_group %0;" :: "n"(n))

// ---------------------------------------------------------------------------
// Transpose W[h][H][D] -> g_WT[qkv][h][D][H], tf32-rounded. grid (48,36), 256t.
// ---------------------------------------------------------------------------
__global__ __launch_bounds__(256) void transpose_W(
    const float* __restrict__ Wq, const float* __restrict__ Wk,
    const float* __restrict__ Wv)
{
    const int qkv = blockIdx.y / NH_;
    const int h   = blockIdx.y % NH_;
    const float* W = (qkv == 0 ? Wq : (qkv == 1 ? Wk : Wv)) + (size_t)h * H_ * D_;
    float* WT = g_WT + (size_t)blockIdx.y * D_ * H_;

    const int kt = (blockIdx.x >> 1) * 32;   // k-tile (H dim)
    const int nt = (blockIdx.x & 1) * 32;    // n-tile (D dim)

    __shared__ float t[32][33];
    const int r  = threadIdx.x >> 3;          // 0..31
    const int c4 = (threadIdx.x & 7) * 4;     // 0,4,..28

    float4 v = *(const float4*)&W[(size_t)(kt + r) * D_ + nt + c4];
    t[r][c4 + 0] = v.x; t[r][c4 + 1] = v.y; t[r][c4 + 2] = v.z; t[r][c4 + 3] = v.w;
    __syncthreads();
    float4 o;
    o.x = __uint_as_float(f2tf32(t[c4 + 0][r]));
    o.y = __uint_as_float(f2tf32(t[c4 + 1][r]));
    o.z = __uint_as_float(f2tf32(t[c4 + 2][r]));
    o.w = __uint_as_float(f2tf32(t[c4 + 3][r]));
    *(float4*)&WT[(size_t)(nt + r) * H_ + kt + c4] = o;
}

// ---------------------------------------------------------------------------
// QKV projection (per-group launch): grid (64, 3), blockIdx.y = qkv.
// 512 thr (16 warps), block 128x256 (4 heads of group `grp`), warp 32x64.
// ---------------------------------------------------------------------------
#define APITCH 36   // 36 % 32 == 4; row stride 144B = 9*16B -> LDSM conflict-free
#define KSTAGES (H_ / 32)   // 24
#define PROJ_SMEM ((2 * 128 * APITCH + 2 * 256 * APITCH) * 4)   // 110592 B
__global__ __launch_bounds__(512) void qkv_proj_tc(
    const float* __restrict__ e1, const float* __restrict__ e2,
    const float* __restrict__ e3,
    const float* __restrict__ bq, const float* __restrict__ bk,
    const float* __restrict__ bv, int grp)
{
    const int qkv = blockIdx.y;

    const float* WT   = g_WT + ((size_t)(qkv * NH_ + grp * 4)) * D_ * H_;
    const float* bias = (qkv == 0 ? bq : (qkv == 1 ? bk : bv)) + grp * 4 * D_;
    const float* x    = (grp == 0 ? e1 : (grp == 1 ? e2 : e3));

    const int m0  = blockIdx.x * 128;
    const int tid = threadIdx.x;
    const int w    = tid >> 5;
    const int lane = tid & 31;
    const int g    = lane >> 2;
    const int c    = lane & 3;
    const int m0w  = (w & 3) * 32;
    const int n0w  = (w >> 2) * 64;

    const int mrow = lane & 7;
    const int msel = lane >> 3;
    const int a_row = (msel & 1) * 8 + mrow;
    const int a_col = (msel >> 1) * 4;
    const int b_row = (msel >> 1) * 8 + mrow;
    const int b_col = (msel & 1) * 4;

    extern __shared__ float psm[];
    float* As0 = psm;
    float* Bs0 = psm + 2 * 128 * APITCH;
    const uint32_t AsU[2] = { (uint32_t)__cvta_generic_to_shared(As0),
                              (uint32_t)__cvta_generic_to_shared(As0 + 128 * APITCH) };
    const uint32_t BsU[2] = { (uint32_t)__cvta_generic_to_shared(Bs0),
                              (uint32_t)__cvta_generic_to_shared(Bs0 + 256 * APITCH) };

    const int f_row = tid >> 3;
    const int f_c4  = (tid & 7) * 4;

    #pragma unroll
    for (int p = 0; p < 2; p++) {
        int row = f_row + p * 64;
        cp16(AsU[0] + (uint32_t)((row * APITCH + f_c4) * 4),
             &x[(size_t)(m0 + row) * H_ + f_c4]);
    }
    #pragma unroll
    for (int p = 0; p < 4; p++) {
        int row = f_row + p * 64;
        cp16(BsU[0] + (uint32_t)((row * APITCH + f_c4) * 4),
             &WT[(size_t)row * H_ + f_c4]);
    }
    CP_COMMIT();

    float Cf[2][8][4] = {};

    for (int s = 0; s < KSTAGES; s++) {
        CP_WAIT(0);
        __syncthreads();

        if (s + 1 < KSTAGES) {
            const int kc = (s + 1) * 32;
            const int nb = (s + 1) & 1;
            #pragma unroll
            for (int p = 0; p < 2; p++) {
                int row = f_row + p * 64;
                cp16(AsU[nb] + (uint32_t)((row * APITCH + f_c4) * 4),
                     &x[(size_t)(m0 + row) * H_ + kc + f_c4]);
            }
            #pragma unroll
            for (int p = 0; p < 4; p++) {
                int row = f_row + p * 64;
                cp16(BsU[nb] + (uint32_t)((row * APITCH + f_c4) * 4),
                     &WT[(size_t)row * H_ + kc + f_c4]);
            }
            CP_COMMIT();
        }

        const uint32_t aBase = AsU[s & 1];
        const uint32_t bBase = BsU[s & 1];
        #pragma unroll
        for (int k0 = 0; k0 < 32; k0 += 8) {
            uint32_t a[2][4], b[4][4];
            #pragma unroll
            for (int ma = 0; ma < 2; ma++)
                ldsm_x4(a[ma], aBase + (uint32_t)(((m0w + ma * 16 + a_row) * APITCH
                                                   + k0 + a_col) * 4));
            #pragma unroll
            for (int p = 0; p < 4; p++)
                ldsm_x4(b[p], bBase + (uint32_t)(((n0w + p * 16 + b_row) * APITCH
                                                  + k0 + b_col) * 4));
            #pragma unroll
            for (int na = 0; na < 8; na++) {
                uint32_t b0 = b[na >> 1][(na & 1) * 2];
                uint32_t b1 = b[na >> 1][(na & 1) * 2 + 1];
                #pragma unroll
                for (int ma = 0; ma < 2; ma++)
                    mma_tf32(Cf[ma][na], a[ma][0], a[ma][1], a[ma][2], a[ma][3],
                             b0, b1);
            }
        }
    }

    const int h = grp * 4 + (w >> 2);
    if (qkv < 2) {
        float* out = (qkv == 0) ? g_Q : g_K;
        const float scale = (qkv == 0) ? (SCALE_ * LOG2E_) : 1.0f;
        #pragma unroll
        for (int ma = 0; ma < 2; ma++) {
            #pragma unroll
            for (int na = 0; na < 8; na++) {
                int d0 = na * 8 + 2 * c;
                float b0 = bias[n0w + d0], b1 = bias[n0w + d0 + 1];
                #pragma unroll
                for (int half = 0; half < 2; half++) {
                    int m = m0 + m0w + ma * 16 + g + half * 8;
                    int bb = m >> 11;
                    int sq = m & (S_ - 1);
                    size_t base = (((size_t)bb * NH_ + h) * S_ + sq) * D_ + d0;
                    float2 o;
                    o.x = __uint_as_float(f2tf32((Cf[ma][na][half * 2 + 0] + b0) * scale));
                    o.y = __uint_as_float(f2tf32((Cf[ma][na][half * 2 + 1] + b1) * scale));
                    *(float2*)&out[base] = o;
                }
            }
        }
    } else {
        #pragma unroll
        for (int ma = 0; ma < 2; ma++) {
            #pragma unroll
            for (int na = 0; na < 8; na++) {
                int d0 = na * 8 + 2 * c;
                float b0 = bias[n0w + d0], b1 = bias[n0w + d0 + 1];
                #pragma unroll
                for (int half = 0; half < 2; half++) {
                    int m = m0 + m0w + ma * 16 + g + half * 8;
                    int bb = m >> 11;
                    int sq = m & (S_ - 1);
                    float* VT = g_VT + ((size_t)bb * NH_ + h) * D_ * S_;
                    VT[(size_t)d0 * S_ + sq] =
                        __uint_as_float(f2tf32(Cf[ma][na][half * 2 + 0] + b0));
                    VT[(size_t)(d0 + 1) * S_ + sq] =
                        __uint_as_float(f2tf32(Cf[ma][na][half * 2 + 1] + b1));
                }
            }
        }
    }
}

// ---------------------------------------------------------------------------
// Flash attention (per-group launch): grid (16, 16), blockIdx.y = bb*4 + e
// (head = grp*4 + e). 128 thr (4 warps), warp 32 q-rows x 64 keys.
// cp.async ping pipeline, Q-hoist + Ps alias, exp2 softmax. Smem 69632 B.
// ---------------------------------------------------------------------------
#define PITCH 68    // 68 % 32 == 4; row stride 272B = 17*16B -> LDSM conflict-free
__global__ __launch_bounds__(128) void attn_tc(float* __restrict__ out, int grp)
{
    const int bb = blockIdx.y >> 2;
    const int h  = grp * 4 + (blockIdx.y & 3);
    const int bh = bb * NH_ + h;
    const int q0 = blockIdx.x * 128;

    extern __shared__ float sm[];
    float* Qs = sm;                  // [128][PITCH]  (q, d) -> becomes Ps
    float* Ks = Qs + 128 * PITCH;    // [64][PITCH]   (key, d)
    float* Vt = Ks + 64 * PITCH;     // [64][PITCH]   (d, key)
    float* Ps = Qs;                  // alias: Qs dead after fragment hoist
    const uint32_t QsU = (uint32_t)__cvta_generic_to_shared(Qs);
    const uint32_t KsU = (uint32_t)__cvta_generic_to_shared(Ks);
    const uint32_t VtU = (uint32_t)__cvta_generic_to_shared(Vt);
    const uint32_t PsU = QsU;

    const float* Qg  = g_Q  + (size_t)bh * S_ * D_;
    const float* Kg  = g_K  + (size_t)bh * S_ * D_;
    const float* VTg = g_VT + (size_t)bh * D_ * S_;

    const int tid  = threadIdx.x;
    const int w    = tid >> 5;
    const int lane = tid & 31;
    const int g    = lane >> 2;
    const int c    = lane & 3;
    const int m0   = w * 32;

    const int mrow = lane & 7;
    const int msel = lane >> 3;
    const int a_row = (msel & 1) * 8 + mrow;
    const int a_col = (msel >> 1) * 4;
    const int b_row = (msel >> 1) * 8 + mrow;
    const int b_col = (msel & 1) * 4;

    const uint32_t aQ0 = QsU + (uint32_t)(((m0 + a_row) * PITCH + a_col) * 4);
    const uint32_t aQ1 = QsU + (uint32_t)(((m0 + 16 + a_row) * PITCH + a_col) * 4);
    const uint32_t aP0 = PsU + (uint32_t)(((m0 + a_row) * PITCH + a_col) * 4);
    const uint32_t aP1 = PsU + (uint32_t)(((m0 + 16 + a_row) * PITCH + a_col) * 4);

    const int f_row = tid >> 4;            // +p*8 rows
    const int f_c4  = (tid & 15) * 4;

    // -------- prologue: start K0/V0 copies, then load Q --------
    #pragma unroll
    for (int p = 0; p < 8; p++) {
        int row = f_row + p * 8;
        cp16(KsU + (uint32_t)((row * PITCH + f_c4) * 4),
             &Kg[(size_t)row * D_ + f_c4]);
        cp16(VtU + (uint32_t)((row * PITCH + f_c4) * 4),
             &VTg[(size_t)row * S_ + f_c4]);
    }
    CP_COMMIT();

    #pragma unroll
    for (int p = 0; p < 16; p++) {
        int idx = tid + p * 128;
        int row = idx >> 4;
        int c4  = (idx & 15) * 4;
        float4 v = *(const float4*)&Qg[(size_t)(q0 + row) * D_ + c4];
        float* d = &Qs[row * PITCH + c4];
        d[0] = __uint_as_float(f2tf32(v.x));
        d[1] = __uint_as_float(f2tf32(v.y));
        d[2] = __uint_as_float(f2tf32(v.z));
        d[3] = __uint_as_float(f2tf32(v.w));
    }

    float m_i[2][2], l_i[2][2];
    #pragma unroll
    for (int ma = 0; ma < 2; ma++)
        #pragma unroll
        for (int hf = 0; hf < 2; hf++) { m_i[ma][hf] = -INFINITY; l_i[ma][hf] = 0.0f; }
    float O[2][8][4] = {};

    CP_WAIT(0);
    __syncthreads();   // K0, V0, Q all visible

    // Hoist Q fragments to registers (Ps reuse of Qs is ordered by the
    // tile-0 post-QK __syncthreads).
    uint32_t qf[2][8][4];
    #pragma unroll
    for (int ks = 0; ks < 8; ks++) {
        ldsm_x4(qf[0][ks], aQ0 + (uint32_t)(ks * 32));
        ldsm_x4(qf[1][ks], aQ1 + (uint32_t)(ks * 32));
    }

    for (int kt = 0; kt < S_; kt += 64) {
        const int ktn = (kt + 64 < S_) ? kt + 64 : kt;

        // ---- S = Q K^T ----
        float Sf[2][8][4] = {};
        #pragma unroll
        for (int k0 = 0; k0 < 64; k0 += 8) {
            const int ks = k0 >> 3;
            uint32_t b[4][4];
            #pragma unroll
            for (int p = 0; p < 4; p++)
                ldsm_x4(b[p], KsU + (uint32_t)(((p * 16 + b_row) * PITCH
                                                + k0 + b_col) * 4));
            #pragma unroll
            for (int na = 0; na < 8; na++) {
                uint32_t b0 = b[na >> 1][(na & 1) * 2];
                uint32_t b1 = b[na >> 1][(na & 1) * 2 + 1];
                #pragma unroll
                for (int ma = 0; ma < 2; ma++)
                    mma_tf32(Sf[ma][na], qf[ma][ks][0], qf[ma][ks][1],
                             qf[ma][ks][2], qf[ma][ks][3], b0, b1);
            }
        }
        __syncthreads();   // all warps done reading Ks (and tile-0 hoist done)

        // ---- prefetch K_{i+1} ----
        #pragma unroll
        for (int p = 0; p < 8; p++) {
            int row = f_row + p * 8;
            cp16(KsU + (uint32_t)((row * PITCH + f_c4) * 4),
                 &Kg[(size_t)(ktn + row) * D_ + f_c4]);
        }
        CP_COMMIT();

        // ---- online softmax (exp2 domain) ----
        #pragma unroll
        for (int ma = 0; ma < 2; ma++) {
            #pragma unroll
            for (int hf = 0; hf < 2; hf++) {
                float mx = -INFINITY;
                #pragma unroll
                for (int na = 0; na < 8; na++)
                    mx = fmaxf(mx, fmaxf(Sf[ma][na][hf * 2], Sf[ma][na][hf * 2 + 1]));
                mx = fmaxf(mx, __shfl_xor_sync(0xffffffffu, mx, 1));
                mx = fmaxf(mx, __shfl_xor_sync(0xffffffffu, mx, 2));
                float mnew  = fmaxf(m_i[ma][hf], mx);
                float alpha = ex2(m_i[ma][hf] - mnew);
                m_i[ma][hf] = mnew;
                float rs = 0.0f;
                #pragma unroll
                for (int na = 0; na < 8; na++) {
                    float p0 = ex2(Sf[ma][na][hf * 2]     - mnew);
                    float p1 = ex2(Sf[ma][na][hf * 2 + 1] - mnew);
                    Sf[ma][na][hf * 2]     = p0;
                    Sf[ma][na][hf * 2 + 1] = p1;
                    rs += p0 + p1;
                }
                rs += __shfl_xor_sync(0xffffffffu, rs, 1);
                rs += __shfl_xor_sync(0xffffffffu, rs, 2);
                l_i[ma][hf] = l_i[ma][hf] * alpha + rs;
                #pragma unroll
                for (int na = 0; na < 8; na++) {
                    O[ma][na][hf * 2]     *= alpha;
                    O[ma][na][hf * 2 + 1] *= alpha;
                }
            }
        }

        // ---- stage P (tf32-rounded) into Ps (= old Qs region) ----
        #pragma unroll
        for (int ma = 0; ma < 2; ma++) {
            int r = m0 + ma * 16 + g;
            #pragma unroll
            for (int na = 0; na < 8; na++) {
                float2 p0, p1;
                p0.x = __uint_as_float(f2tf32(Sf[ma][na][0]));
                p0.y = __uint_as_float(f2tf32(Sf[ma][na][1]));
                p1.x = __uint_as_float(f2tf32(Sf[ma][na][2]));
                p1.y = __uint_as_float(f2tf32(Sf[ma][na][3]));
                *(float2*)&Ps[r * PITCH + na * 8 + 2 * c]       = p0;
                *(float2*)&Ps[(r + 8) * PITCH + na * 8 + 2 * c] = p1;
            }
        }

        CP_WAIT(1);          // V_i done; K_{i+1} may stay pending
        __syncthreads();     // Vt visible; Ps ordered

        // ---- O += P V ----
        #pragma unroll
        for (int k0 = 0; k0 < 64; k0 += 8) {
            uint32_t a[2][4], b[4][4];
            ldsm_x4(a[0], aP0 + (uint32_t)(k0 * 4));
            ldsm_x4(a[1], aP1 + (uint32_t)(k0 * 4));
            #pragma unroll
            for (int p = 0; p < 4; p++)
                ldsm_x4(b[p], VtU + (uint32_t)(((p * 16 + b_row) * PITCH
                                                + k0 + b_col) * 4));
            #pragma unroll
            for (int na = 0; na < 8; na++) {
                uint32_t b0 = b[na >> 1][(na & 1) * 2];
                uint32_t b1 = b[na >> 1][(na & 1) * 2 + 1];
                #pragma unroll
                for (int ma = 0; ma < 2; ma++)
                    mma_tf32(O[ma][na], a[ma][0], a[ma][1], a[ma][2], a[ma][3],
                             b0, b1);
            }
        }
        __syncthreads();   // all warps done reading Vt

        // ---- prefetch V_{i+1} ----
        #pragma unroll
        for (int p = 0; p < 8; p++) {
            int row = f_row + p * 8;
            cp16(VtU + (uint32_t)((row * PITCH + f_c4) * 4),
                 &VTg[(size_t)row * S_ + ktn + f_c4]);
        }
        CP_COMMIT();

        CP_WAIT(1);          // K_{i+1} done; V_{i+1} may stay pending
        __syncthreads();
    }

    // Epilogue: normalize and write out[b][s][h*64+d]
    #pragma unroll
    for (int ma = 0; ma < 2; ma++) {
        float inv0 = 1.0f / l_i[ma][0];
        float inv1 = 1.0f / l_i[ma][1];
        int r0 = q0 + m0 + ma * 16 + g;
        #pragma unroll
        for (int na = 0; na < 8; na++) {
            int d0 = na * 8 + 2 * c;
            size_t base0 = ((size_t)bb * S_ + r0) * (NH_ * D_) + h * D_ + d0;
            float2 o0; o0.x = O[ma][na][0] * inv0; o0.y = O[ma][na][1] * inv0;
            *(float2*)&out[base0] = o0;
            size_t base1 = ((size_t)bb * S_ + r0 + 8) * (NH_ * D_) + h * D_ + d0;
            float2 o1; o1.x = O[ma][na][2] * inv1; o1.y = O[ma][na][3] * inv1;
            *(float2*)&out[base1] = o1;
        }
    }
}

// ---------------------------------------------------------------------------
extern "C" void kernel_launch(void* const* d_in, const int* in_sizes, int n_in,
                              void* d_out, int out_size)
{
    const float* e1 = (const float*)d_in[0];
    const float* e2 = (const float*)d_in[1];
    const float* e3 = (const float*)d_in[2];
    const float* Wq = (const float*)d_in[3];
    const float* bq = (const float*)d_in[4];
    const float* Wk = (const float*)d_in[5];
    const float* bk = (const float*)d_in[6];
    const float* Wv = (const float*)d_in[7];
    const float* bv = (const float*)d_in[8];
    float* out = (float*)d_out;

    const int attn_smem = 256 * PITCH * sizeof(float);   // 69632 B

    static bool init_done = false;
    static cudaStream_t s1, s2;
    static cudaEvent_t evFork, evJ1, evJ2;
    if (!init_done) {
        cudaFuncSetAttribute(attn_tc, cudaFuncAttributeMaxDynamicSharedMemorySize,
                             attn_smem);
        cudaFuncSetAttribute(qkv_proj_tc, cudaFuncAttributeMaxDynamicSharedMemorySize,
                             PROJ_SMEM);
        cudaStreamCreateWithFlags(&s1, cudaStreamNonBlocking);
        cudaStreamCreateWithFlags(&s2, cudaStreamNonBlocking);
        cudaEventCreateWithFlags(&evFork, cudaEventDisableTiming);
        cudaEventCreateWithFlags(&evJ1, cudaEventDisableTiming);
        cudaEventCreateWithFlags(&evJ2, cudaEventDisableTiming);
        init_done = true;
    }

    // Per-group pipelines: stream g runs proj(g) then attn(g); groups overlap.
    transpose_W<<<dim3(48, 36), 256>>>(Wq, Wk, Wv);
    cudaEventRecord(evFork, 0);
    cudaStreamWaitEvent(s1, evFork, 0);
    cudaStreamWaitEvent(s2, evFork, 0);

    dim3 gproj((B_ * S_) / 128, 3);
    dim3 gattn(S_ / 128, (B_ * 4));
    qkv_proj_tc<<<gproj, 512, PROJ_SMEM, 0>>>(e1, e2, e3, bq, bk, bv, 0);
    qkv_proj_tc<<<gproj, 512, PROJ_SMEM, s1>>>(e1, e2, e3, bq, bk, bv, 1);
    qkv_proj_tc<<<gproj, 512, PROJ_SMEM, s2>>>(e1, e2, e3, bq, bk, bv, 2);
    attn_tc<<<gattn, 128, attn_smem, 0>>>(out, 0);
    attn_tc<<<gattn, 128, attn_smem, s1>>>(out, 1);
    attn_tc<<<gattn, 128, attn_smem, s2>>>(out, 2);

    cudaEventRecord(evJ1, s1);
    cudaEventRecord(evJ2, s2);
    cudaStreamWaitEvent(0, evJ1, 0);
    cudaStreamWaitEvent(0, evJ2, 0);
}

// round 17
// speedup vs baseline: 1.3436x; 1.0041x over previous
#include <cuda_runtime.h>
#include <math.h>
#include <stdint.h>

#define B_  4
#define S_  2048
#define H_  768
#define NH_ 12
#define D_  64
#define SCALE_ 0.125f          // 1/sqrt(64)
#define LOG2E_ 1.44269504089f

// Scratch. Q/K layout [b][h][s][d]; VT layout [b][h][d][s]
__device__ float g_Q[(size_t)B_ * NH_ * S_ * D_];
__device__ float g_K[(size_t)B_ * NH_ * S_ * D_];
__device__ float g_VT[(size_t)B_ * NH_ * D_ * S_];
// Transposed weights [qkv][h][d][H] (tf32-rounded)
__device__ float g_WT[(size_t)3 * NH_ * D_ * H_];

// ---------------------------------------------------------------------------
__device__ __forceinline__ uint32_t f2tf32(float f) {
    uint32_t u;
    asm("cvt.rna.tf32.f32 %0, %1;" : "=r"(u) : "f"(f));
    return u;
}
__device__ __forceinline__ float ex2(float x) {
    float r;
    asm("ex2.approx.f32 %0, %1;" : "=f"(r) : "f"(x));
    return r;
}
__device__ __forceinline__ void mma_tf32(float c[4], uint32_t a0, uint32_t a1,
                                         uint32_t a2, uint32_t a3,
                                         uint32_t b0, uint32_t b1) {
    asm volatile(
        "mma.sync.aligned.m16n8k8.row.col.f32.tf32.tf32.f32 "
        "{%0,%1,%2,%3}, {%4,%5,%6,%7}, {%8,%9}, {%0,%1,%2,%3};"
        : "+f"(c[0]), "+f"(c[1]), "+f"(c[2]), "+f"(c[3])
        : "r"(a0), "r"(a1), "r"(a2), "r"(a3), "r"(b0), "r"(b1));
}
// One ldmatrix.x4: 4 m8n8(b16) tiles = 4 fragment registers.
__device__ __forceinline__ void ldsm_x4(uint32_t r[4], uint32_t addr) {
    asm volatile(
        "ldmatrix.sync.aligned.m8n8.x4.shared.b16 {%0,%1,%2,%3}, [%4];"
        : "=r"(r[0]), "=r"(r[1]), "=r"(r[2]), "=r"(r[3]) : "r"(addr));
}
__device__ __forceinline__ void cp16(uint32_t smem, const void* g) {
    asm volatile("cp.async.cg.shared.global [%0], [%1], 16;"
                 :: "r"(smem), "l"(g));
}
#define CP_COMMIT() asm volatile("cp.async.commit_group;")
#define CP_WAIT(n)  asm volatile("cp.async.wait_group %0;" :: "n"(n))

// ---------------------------------------------------------------------------
// Transpose W[h][H][D] -> g_WT[qkv][h][D][H], tf32-rounded. grid (48,36), 256t.
// ---------------------------------------------------------------------------
__global__ __launch_bounds__(256) void transpose_W(
    const float* __restrict__ Wq, const float* __restrict__ Wk,
    const float* __restrict__ Wv)
{
    const int qkv = blockIdx.y / NH_;
    const int h   = blockIdx.y % NH_;
    const float* W = (qkv == 0 ? Wq : (qkv == 1 ? Wk : Wv)) + (size_t)h * H_ * D_;
    float* WT = g_WT + (size_t)blockIdx.y * D_ * H_;

    const int kt = (blockIdx.x >> 1) * 32;   // k-tile (H dim)
    const int nt = (blockIdx.x & 1) * 32;    // n-tile (D dim)

    __shared__ float t[32][33];
    const int r  = threadIdx.x >> 3;          // 0..31
    const int c4 = (threadIdx.x & 7) * 4;     // 0,4,..28

    float4 v = *(const float4*)&W[(size_t)(kt + r) * D_ + nt + c4];
    t[r][c4 + 0] = v.x; t[r][c4 + 1] = v.y; t[r][c4 + 2] = v.z; t[r][c4 + 3] = v.w;
    __syncthreads();
    float4 o;
    o.x = __uint_as_float(f2tf32(t[c4 + 0][r]));
    o.y = __uint_as_float(f2tf32(t[c4 + 1][r]));
    o.z = __uint_as_float(f2tf32(t[c4 + 2][r]));
    o.w = __uint_as_float(f2tf32(t[c4 + 3][r]));
    *(float4*)&WT[(size_t)(nt + r) * H_ + kt + c4] = o;
}

// ---------------------------------------------------------------------------
// QKV projection (per-group launch, R15 winner unchanged): grid (64, 3).
// 512 thr (16 warps), block 128x256 (4 heads of group `grp`), warp 32x64.
// ---------------------------------------------------------------------------
#define APITCH 36   // 36 % 32 == 4; row stride 144B = 9*16B -> LDSM conflict-free
#define KSTAGES (H_ / 32)   // 24
#define PROJ_SMEM ((2 * 128 * APITCH + 2 * 256 * APITCH) * 4)   // 110592 B
__global__ __launch_bounds__(512) void qkv_proj_tc(
    const float* __restrict__ e1, const float* __restrict__ e2,
    const float* __restrict__ e3,
    const float* __restrict__ bq, const float* __restrict__ bk,
    const float* __restrict__ bv, int grp)
{
    const int qkv = blockIdx.y;

    const float* WT   = g_WT + ((size_t)(qkv * NH_ + grp * 4)) * D_ * H_;
    const float* bias = (qkv == 0 ? bq : (qkv == 1 ? bk : bv)) + grp * 4 * D_;
    const float* x    = (grp == 0 ? e1 : (grp == 1 ? e2 : e3));

    const int m0  = blockIdx.x * 128;
    const int tid = threadIdx.x;
    const int w    = tid >> 5;
    const int lane = tid & 31;
    const int g    = lane >> 2;
    const int c    = lane & 3;
    const int m0w  = (w & 3) * 32;
    const int n0w  = (w >> 2) * 64;

    const int mrow = lane & 7;
    const int msel = lane >> 3;
    const int a_row = (msel & 1) * 8 + mrow;
    const int a_col = (msel >> 1) * 4;
    const int b_row = (msel >> 1) * 8 + mrow;
    const int b_col = (msel & 1) * 4;

    extern __shared__ float psm[];
    float* As0 = psm;
    float* Bs0 = psm + 2 * 128 * APITCH;
    const uint32_t AsU[2] = { (uint32_t)__cvta_generic_to_shared(As0),
                              (uint32_t)__cvta_generic_to_shared(As0 + 128 * APITCH) };
    const uint32_t BsU[2] = { (uint32_t)__cvta_generic_to_shared(Bs0),
                              (uint32_t)__cvta_generic_to_shared(Bs0 + 256 * APITCH) };

    const int f_row = tid >> 3;
    const int f_c4  = (tid & 7) * 4;

    #pragma unroll
    for (int p = 0; p < 2; p++) {
        int row = f_row + p * 64;
        cp16(AsU[0] + (uint32_t)((row * APITCH + f_c4) * 4),
             &x[(size_t)(m0 + row) * H_ + f_c4]);
    }
    #pragma unroll
    for (int p = 0; p < 4; p++) {
        int row = f_row + p * 64;
        cp16(BsU[0] + (uint32_t)((row * APITCH + f_c4) * 4),
             &WT[(size_t)row * H_ + f_c4]);
    }
    CP_COMMIT();

    float Cf[2][8][4] = {};

    for (int s = 0; s < KSTAGES; s++) {
        CP_WAIT(0);
        __syncthreads();

        if (s + 1 < KSTAGES) {
            const int kc = (s + 1) * 32;
            const int nb = (s + 1) & 1;
            #pragma unroll
            for (int p = 0; p < 2; p++) {
                int row = f_row + p * 64;
                cp16(AsU[nb] + (uint32_t)((row * APITCH + f_c4) * 4),
                     &x[(size_t)(m0 + row) * H_ + kc + f_c4]);
            }
            #pragma unroll
            for (int p = 0; p < 4; p++) {
                int row = f_row + p * 64;
                cp16(BsU[nb] + (uint32_t)((row * APITCH + f_c4) * 4),
                     &WT[(size_t)row * H_ + kc + f_c4]);
            }
            CP_COMMIT();
        }

        const uint32_t aBase = AsU[s & 1];
        const uint32_t bBase = BsU[s & 1];
        #pragma unroll
        for (int k0 = 0; k0 < 32; k0 += 8) {
            uint32_t a[2][4], b[4][4];
            #pragma unroll
            for (int ma = 0; ma < 2; ma++)
                ldsm_x4(a[ma], aBase + (uint32_t)(((m0w + ma * 16 + a_row) * APITCH
                                                   + k0 + a_col) * 4));
            #pragma unroll
            for (int p = 0; p < 4; p++)
                ldsm_x4(b[p], bBase + (uint32_t)(((n0w + p * 16 + b_row) * APITCH
                                                  + k0 + b_col) * 4));
            #pragma unroll
            for (int na = 0; na < 8; na++) {
                uint32_t b0 = b[na >> 1][(na & 1) * 2];
                uint32_t b1 = b[na >> 1][(na & 1) * 2 + 1];
                #pragma unroll
                for (int ma = 0; ma < 2; ma++)
                    mma_tf32(Cf[ma][na], a[ma][0], a[ma][1], a[ma][2], a[ma][3],
                             b0, b1);
            }
        }
    }

    const int h = grp * 4 + (w >> 2);
    if (qkv < 2) {
        float* out = (qkv == 0) ? g_Q : g_K;
        const float scale = (qkv == 0) ? (SCALE_ * LOG2E_) : 1.0f;
        #pragma unroll
        for (int ma = 0; ma < 2; ma++) {
            #pragma unroll
            for (int na = 0; na < 8; na++) {
                int d0 = na * 8 + 2 * c;
                float b0 = bias[n0w + d0], b1 = bias[n0w + d0 + 1];
                #pragma unroll
                for (int half = 0; half < 2; half++) {
                    int m = m0 + m0w + ma * 16 + g + half * 8;
                    int bb = m >> 11;
                    int sq = m & (S_ - 1);
                    size_t base = (((size_t)bb * NH_ + h) * S_ + sq) * D_ + d0;
                    float2 o;
                    o.x = __uint_as_float(f2tf32((Cf[ma][na][half * 2 + 0] + b0) * scale));
                    o.y = __uint_as_float(f2tf32((Cf[ma][na][half * 2 + 1] + b1) * scale));
                    *(float2*)&out[base] = o;
                }
            }
        }
    } else {
        #pragma unroll
        for (int ma = 0; ma < 2; ma++) {
            #pragma unroll
            for (int na = 0; na < 8; na++) {
                int d0 = na * 8 + 2 * c;
                float b0 = bias[n0w + d0], b1 = bias[n0w + d0 + 1];
                #pragma unroll
                for (int half = 0; half < 2; half++) {
                    int m = m0 + m0w + ma * 16 + g + half * 8;
                    int bb = m >> 11;
                    int sq = m & (S_ - 1);
                    float* VT = g_VT + ((size_t)bb * NH_ + h) * D_ * S_;
                    VT[(size_t)d0 * S_ + sq] =
                        __uint_as_float(f2tf32(Cf[ma][na][half * 2 + 0] + b0));
                    VT[(size_t)(d0 + 1) * S_ + sq] =
                        __uint_as_float(f2tf32(Cf[ma][na][half * 2 + 1] + b1));
                }
            }
        }
    }
}

// ---------------------------------------------------------------------------
// Flash attention (per-group launch): grid (16, 16), blockIdx.y = bb*4 + e.
// 128 thr (4 warps), warp 32 q-rows x 64 keys. K single-buffered with
// fine-grained prefetch; V DOUBLE-buffered (prefetch issued before PV, no
// post-PV barrier). 3 syncthreads/tile. Q-hoist + Ps alias, exp2 softmax.
// Smem 87040 B (2 CTAs/SM).
// ---------------------------------------------------------------------------
#define PITCH 68    // 68 % 32 == 4; row stride 272B = 17*16B -> LDSM conflict-free
__global__ __launch_bounds__(128) void attn_tc(float* __restrict__ out, int grp)
{
    const int bb = blockIdx.y >> 2;
    const int h  = grp * 4 + (blockIdx.y & 3);
    const int bh = bb * NH_ + h;
    const int q0 = blockIdx.x * 128;

    extern __shared__ float sm[];
    float* Qs = sm;                  // [128][PITCH]  (q, d) -> becomes Ps
    float* Ps = Qs;                  // alias: Qs dead after fragment hoist
    const uint32_t QsU = (uint32_t)__cvta_generic_to_shared(Qs);
    const uint32_t PsU = QsU;
    const uint32_t KsU = (uint32_t)__cvta_generic_to_shared(sm + 128 * PITCH);
    const uint32_t VtU[2] = {
        (uint32_t)__cvta_generic_to_shared(sm + 192 * PITCH),
        (uint32_t)__cvta_generic_to_shared(sm + 256 * PITCH) };

    const float* Qg  = g_Q  + (size_t)bh * S_ * D_;
    const float* Kg  = g_K  + (size_t)bh * S_ * D_;
    const float* VTg = g_VT + (size_t)bh * D_ * S_;

    const int tid  = threadIdx.x;
    const int w    = tid >> 5;
    const int lane = tid & 31;
    const int g    = lane >> 2;
    const int c    = lane & 3;
    const int m0   = w * 32;

    const int mrow = lane & 7;
    const int msel = lane >> 3;
    const int a_row = (msel & 1) * 8 + mrow;
    const int a_col = (msel >> 1) * 4;
    const int b_row = (msel >> 1) * 8 + mrow;
    const int b_col = (msel & 1) * 4;

    const uint32_t aQ0 = QsU + (uint32_t)(((m0 + a_row) * PITCH + a_col) * 4);
    const uint32_t aQ1 = QsU + (uint32_t)(((m0 + 16 + a_row) * PITCH + a_col) * 4);
    const uint32_t aP0 = PsU + (uint32_t)(((m0 + a_row) * PITCH + a_col) * 4);
    const uint32_t aP1 = PsU + (uint32_t)(((m0 + 16 + a_row) * PITCH + a_col) * 4);

    const int f_row = tid >> 4;            // +p*8 rows
    const int f_c4  = (tid & 15) * 4;

    // -------- prologue: commit K0 (group), V0 (group), load Q --------
    #pragma unroll
    for (int p = 0; p < 8; p++) {
        int row = f_row + p * 8;
        cp16(KsU + (uint32_t)((row * PITCH + f_c4) * 4),
             &Kg[(size_t)row * D_ + f_c4]);
    }
    CP_COMMIT();
    #pragma unroll
    for (int p = 0; p < 8; p++) {
        int row = f_row + p * 8;
        cp16(VtU[0] + (uint32_t)((row * PITCH + f_c4) * 4),
             &VTg[(size_t)row * S_ + f_c4]);
    }
    CP_COMMIT();

    #pragma unroll
    for (int p = 0; p < 16; p++) {
        int idx = tid + p * 128;
        int row = idx >> 4;
        int c4  = (idx & 15) * 4;
        float4 v = *(const float4*)&Qg[(size_t)(q0 + row) * D_ + c4];
        float* d = &Qs[row * PITCH + c4];
        d[0] = __uint_as_float(f2tf32(v.x));
        d[1] = __uint_as_float(f2tf32(v.y));
        d[2] = __uint_as_float(f2tf32(v.z));
        d[3] = __uint_as_float(f2tf32(v.w));
    }

    float m_i[2][2], l_i[2][2];
    #pragma unroll
    for (int ma = 0; ma < 2; ma++)
        #pragma unroll
        for (int hf = 0; hf < 2; hf++) { m_i[ma][hf] = -INFINITY; l_i[ma][hf] = 0.0f; }
    float O[2][8][4] = {};

    CP_WAIT(0);
    __syncthreads();   // K0, V0, Q all visible

    // Hoist Q fragments (Ps reuse of Qs ordered by tile-0 post-QK sync).
    uint32_t qf[2][8][4];
    #pragma unroll
    for (int ks = 0; ks < 8; ks++) {
        ldsm_x4(qf[0][ks], aQ0 + (uint32_t)(ks * 32));
        ldsm_x4(qf[1][ks], aQ1 + (uint32_t)(ks * 32));
    }

    #define NTILES (S_ / 64)   // 32
    for (int t = 0; t < NTILES; t++) {
        const int buf = t & 1;
        const int ktn = (t + 1 < NTILES) ? (t + 1) * 64 : t * 64;

        // ---- S = Q K^T (reads Ks = K_t) ----
        float Sf[2][8][4] = {};
        #pragma unroll
        for (int k0 = 0; k0 < 64; k0 += 8) {
            const int ks = k0 >> 3;
            uint32_t b[4][4];
            #pragma unroll
            for (int p = 0; p < 4; p++)
                ldsm_x4(b[p], KsU + (uint32_t)(((p * 16 + b_row) * PITCH
                                                + k0 + b_col) * 4));
            #pragma unroll
            for (int na = 0; na < 8; na++) {
                uint32_t b0 = b[na >> 1][(na & 1) * 2];
                uint32_t b1 = b[na >> 1][(na & 1) * 2 + 1];
                #pragma unroll
                for (int ma = 0; ma < 2; ma++)
                    mma_tf32(Sf[ma][na], qf[ma][ks][0], qf[ma][ks][1],
                             qf[ma][ks][2], qf[ma][ks][3], b0, b1);
            }
        }
        __syncthreads();   // all warps done with Ks (and PV_{t-1} readers past)

        // ---- prefetch K_{t+1} into Ks (group) ----
        #pragma unroll
        for (int p = 0; p < 8; p++) {
            int row = f_row + p * 8;
            cp16(KsU + (uint32_t)((row * PITCH + f_c4) * 4),
                 &Kg[(size_t)(ktn + row) * D_ + f_c4]);
        }
        CP_COMMIT();

        // ---- online softmax (exp2 domain) ----
        #pragma unroll
        for (int ma = 0; ma < 2; ma++) {
            #pragma unroll
            for (int hf = 0; hf < 2; hf++) {
                float mx = -INFINITY;
                #pragma unroll
                for (int na = 0; na < 8; na++)
                    mx = fmaxf(mx, fmaxf(Sf[ma][na][hf * 2], Sf[ma][na][hf * 2 + 1]));
                mx = fmaxf(mx, __shfl_xor_sync(0xffffffffu, mx, 1));
                mx = fmaxf(mx, __shfl_xor_sync(0xffffffffu, mx, 2));
                float mnew  = fmaxf(m_i[ma][hf], mx);
                float alpha = ex2(m_i[ma][hf] - mnew);
                m_i[ma][hf] = mnew;
                float rs = 0.0f;
                #pragma unroll
                for (int na = 0; na < 8; na++) {
                    float p0 = ex2(Sf[ma][na][hf * 2]     - mnew);
                    float p1 = ex2(Sf[ma][na][hf * 2 + 1] - mnew);
                    Sf[ma][na][hf * 2]     = p0;
                    Sf[ma][na][hf * 2 + 1] = p1;
                    rs += p0 + p1;
                }
                rs += __shfl_xor_sync(0xffffffffu, rs, 1);
                rs += __shfl_xor_sync(0xffffffffu, rs, 2);
                l_i[ma][hf] = l_i[ma][hf] * alpha + rs;
                #pragma unroll
                for (int na = 0; na < 8; na++) {
                    O[ma][na][hf * 2]     *= alpha;
                    O[ma][na][hf * 2 + 1] *= alpha;
                }
            }
        }

        // ---- prefetch V_{t+1} into the idle buffer (group; no barrier) ----
        #pragma unroll
        for (int p = 0; p < 8; p++) {
            int row = f_row + p * 8;
            cp16(VtU[buf ^ 1] + (uint32_t)((row * PITCH + f_c4) * 4),
                 &VTg[(size_t)row * S_ + ktn + f_c4]);
        }
        CP_COMMIT();

        // ---- stage P (tf32-rounded) into Ps ----
        #pragma unroll
        for (int ma = 0; ma < 2; ma++) {
            int r = m0 + ma * 16 + g;
            #pragma unroll
            for (int na = 0; na < 8; na++) {
                float2 p0, p1;
                p0.x = __uint_as_float(f2tf32(Sf[ma][na][0]));
                p0.y = __uint_as_float(f2tf32(Sf[ma][na][1]));
                p1.x = __uint_as_float(f2tf32(Sf[ma][na][2]));
                p1.y = __uint_as_float(f2tf32(Sf[ma][na][3]));
                *(float2*)&Ps[r * PITCH + na * 8 + 2 * c]       = p0;
                *(float2*)&Ps[(r + 8) * PITCH + na * 8 + 2 * c] = p1;
            }
        }

        // ---- wait V_t (allow K_{t+1}, V_{t+1} pending), make visible ----
        CP_WAIT(2);
        __syncthreads();

        // ---- O += P V_t (reads Vt[buf], Ps) ----
        #pragma unroll
        for (int k0 = 0; k0 < 64; k0 += 8) {
            uint32_t a[2][4], b[4][4];
            ldsm_x4(a[0], aP0 + (uint32_t)(k0 * 4));
            ldsm_x4(a[1], aP1 + (uint32_t)(k0 * 4));
            #pragma unroll
            for (int p = 0; p < 4; p++)
                ldsm_x4(b[p], VtU[buf] + (uint32_t)(((p * 16 + b_row) * PITCH
                                                     + k0 + b_col) * 4));
            #pragma unroll
            for (int na = 0; na < 8; na++) {
                uint32_t b0 = b[na >> 1][(na & 1) * 2];
                uint32_t b1 = b[na >> 1][(na & 1) * 2 + 1];
                #pragma unroll
                for (int ma = 0; ma < 2; ma++)
                    mma_tf32(O[ma][na], a[ma][0], a[ma][1], a[ma][2], a[ma][3],
                             b0, b1);
            }
        }

        // ---- wait K_{t+1} (allow V_{t+1} pending), make visible ----
        CP_WAIT(1);
        __syncthreads();
    }

    // Epilogue: normalize and write out[b][s][h*64+d]
    #pragma unroll
    for (int ma = 0; ma < 2; ma++) {
        float inv0 = 1.0f / l_i[ma][0];
        float inv1 = 1.0f / l_i[ma][1];
        int r0 = q0 + m0 + ma * 16 + g;
        #pragma unroll
        for (int na = 0; na < 8; na++) {
            int d0 = na * 8 + 2 * c;
            size_t base0 = ((size_t)bb * S_ + r0) * (NH_ * D_) + h * D_ + d0;
            float2 o0; o0.x = O[ma][na][0] * inv0; o0.y = O[ma][na][1] * inv0;
            *(float2*)&out[base0] = o0;
            size_t base1 = ((size_t)bb * S_ + r0 + 8) * (NH_ * D_) + h * D_ + d0;
            float2 o1; o1.x = O[ma][na][2] * inv1; o1.y = O[ma][na][3] * inv1;
            *(float2*)&out[base1] = o1;
        }
    }
}

// ---------------------------------------------------------------------------
extern "C" void kernel_launch(void* const* d_in, const int* in_sizes, int n_in,
                              void* d_out, int out_size)
{
    const float* e1 = (const float*)d_in[0];
    const float* e2 = (const float*)d_in[1];
    const float* e3 = (const float*)d_in[2];
    const float* Wq = (const float*)d_in[3];
    const float* bq = (const float*)d_in[4];
    const float* Wk = (const float*)d_in[5];
    const float* bk = (const float*)d_in[6];
    const float* Wv = (const float*)d_in[7];
    const float* bv = (const float*)d_in[8];
    float* out = (float*)d_out;

    const int attn_smem = 320 * PITCH * sizeof(float);   // 87040 B

    static bool init_done = false;
    static cudaStream_t s1, s2;
    static cudaEvent_t evFork, evJ1, evJ2;
    if (!init_done) {
        cudaFuncSetAttribute(attn_tc, cudaFuncAttributeMaxDynamicSharedMemorySize,
                             attn_smem);
        cudaFuncSetAttribute(qkv_proj_tc, cudaFuncAttributeMaxDynamicSharedMemorySize,
                             PROJ_SMEM);
        cudaStreamCreateWithFlags(&s1, cudaStreamNonBlocking);
        cudaStreamCreateWithFlags(&s2, cudaStreamNonBlocking);
        cudaEventCreateWithFlags(&evFork, cudaEventDisableTiming);
        cudaEventCreateWithFlags(&evJ1, cudaEventDisableTiming);
        cudaEventCreateWithFlags(&evJ2, cudaEventDisableTiming);
        init_done = true;
    }

    // Per-group pipelines: stream g runs proj(g) then attn(g); groups overlap.
    transpose_W<<<dim3(48, 36), 256>>>(Wq, Wk, Wv);
    cudaEventRecord(evFork, 0);
    cudaStreamWaitEvent(s1, evFork, 0);
    cudaStreamWaitEvent(s2, evFork, 0);

    dim3 gproj((B_ * S_) / 128, 3);
    dim3 gattn(S_ / 128, (B_ * 4));
    qkv_proj_tc<<<gproj, 512, PROJ_SMEM, 0>>>(e1, e2, e3, bq, bk, bv, 0);
    qkv_proj_tc<<<gproj, 512, PROJ_SMEM, s1>>>(e1, e2, e3, bq, bk, bv, 1);
    qkv_proj_tc<<<gproj, 512, PROJ_SMEM, s2>>>(e1, e2, e3, bq, bk, bv, 2);
    attn_tc<<<gattn, 128, attn_smem, 0>>>(out, 0);
    attn_tc<<<gattn, 128, attn_smem, s1>>>(out, 1);
    attn_tc<<<gattn, 128, attn_smem, s2>>>(out, 2);

    cudaEventRecord(evJ1, s1);
    cudaEventRecord(evJ2, s2);
    cudaStreamWaitEvent(0, evJ1, 0);
    cudaStreamWaitEvent(0, evJ2, 0);
}